// round 13
// baseline (speedup 1.0000x reference)
#include <cuda_runtime.h>

#define BINS 64
#define BC 96                      // B*C = 32*3
#define PLANE4 65536               // 512*512/4 float4 per (b,c) plane
#define BPP 21                     // chunks per plane (96*21 = 2016 blocks)
#define THREADS 128
#define WARPS (THREADS / 32)       // 4
#define GRID (BC * BPP)            // 2016 = 13.62 blocks/SM -> SINGLE WAVE

// Signed per-(plane,bin) count diff (+input, -target). Zero at module load;
// the last block restores it to zero each call -> graph-replay safe.
__device__ int g_diff[BC * BINS];
__device__ unsigned int g_count;

// bin = clip(floor((v+1)/step), 0, 63). Input domain [-1,1) => result >= 0.
// Exact-edge disagreement with searchsorted is ~1e-6 relative loss noise.
__device__ __forceinline__ int bin_of(float v) {
    return min(__float2int_rd(fmaf(v, 31.5f, 31.5f)), 63);
}

// u16 packing, 2 bins/word: word(w,m,lane) = w*1024 + m*32 + lane (m=bin>>1),
// halfword = bin&1. word % 32 == lane for EVERY bin -> strictly
// conflict-free LDS/STS RMW. Halfword offset from the lane's column base:
__device__ __forceinline__ int slot_of(int b) {
    return ((b >> 1) << 6) | (b & 1);
}

__global__ __launch_bounds__(THREADS, 14)   // cap regs at 36 so 14 blocks fit
void fused_kernel(const float4* __restrict__ inp, const float4* __restrict__ tgt,
                  float* __restrict__ out) {
    __shared__ short hist[WARPS * BINS * 32];  // 16 KB -> 14 blocks/SM
    __shared__ unsigned int s_ticket;
    __shared__ float ssum[WARPS];

    const int tid  = threadIdx.x;
    const int lane = tid & 31;
    const int wid  = tid >> 5;

    int4* z4 = (int4*)hist;
    #pragma unroll
    for (int i = tid; i < (int)sizeof(hist) / 16; i += THREADS)
        z4[i] = make_int4(0, 0, 0, 0);
    __syncthreads();

    // Lane-owned column: halfword index = wid*2048 + lane*2 + slot_of(bin).
    short* h = &hist[wid * 2048 + lane * 2];

    const int plane = blockIdx.x;              // 0..95
    const int chunk = blockIdx.y;              // 0..20
    // Uneven chunking with exact integer bounds (PLANE4 not divisible by 21).
    const int start4 = (chunk * PLANE4) / BPP;
    const int end4   = ((chunk + 1) * PLANE4) / BPP;
    const float4* __restrict__ a = inp + (size_t)plane * PLANE4;
    const float4* __restrict__ b = tgt + (size_t)plane * PLANE4;

    for (int i = start4 + tid; i < end4; i += THREADS) {
        float4 v = __ldcs(&a[i]);              // read-once: streaming
        float4 u = __ldcs(&b[i]);
        h[slot_of(bin_of(v.x))] += 1;
        h[slot_of(bin_of(v.y))] += 1;
        h[slot_of(bin_of(v.z))] += 1;
        h[slot_of(bin_of(v.w))] += 1;
        h[slot_of(bin_of(u.x))] -= 1;
        h[slot_of(bin_of(u.y))] -= 1;
        h[slot_of(bin_of(u.z))] -= 1;
        h[slot_of(bin_of(u.w))] -= 1;
    }
    __syncthreads();

    // Fold: thread t -> bin pair m = t>>2, warp w = t&3. Packed halfword
    // accumulation over 32 lanes (__vadd2: |half-sums| <= ~3200, safe).
    // Rotation (k+t)&31 keeps banks distinct; shfl-combine the 4 warps.
    {
        const int m = tid >> 2;
        const int w = tid & 3;
        const int* words = (const int*)hist;
        int sp = 0;
        #pragma unroll
        for (int k = 0; k < 32; k++)
            sp = __vadd2(sp, words[w * 1024 + m * 32 + ((k + tid) & 31)]);
        sp = __vadd2(sp, __shfl_xor_sync(0xFFFFFFFFu, sp, 1));
        sp = __vadd2(sp, __shfl_xor_sync(0xFFFFFFFFu, sp, 2));
        if (w == 0) {
            int s_even = (int)(short)(sp & 0xFFFF);
            int s_odd  = sp >> 16;
            if (s_even) atomicAdd(&g_diff[plane * BINS + 2 * m], s_even);
            if (s_odd)  atomicAdd(&g_diff[plane * BINS + 2 * m + 1], s_odd);
        }
    }

    // Last block finishes the reduction (no separate kernel launch).
    __threadfence();
    if (tid == 0) s_ticket = atomicAdd(&g_count, 1u);
    __syncthreads();
    if (s_ticket == GRID - 1) {
        float s = 0.0f;
        for (int i = tid; i < BC * BINS; i += THREADS) {
            s += fabsf((float)__ldcg(&g_diff[i]));
            g_diff[i] = 0;                     // restore scratch for replay
        }
        #pragma unroll
        for (int o = 16; o > 0; o >>= 1)
            s += __shfl_down_sync(0xFFFFFFFFu, s, o);
        if (lane == 0) ssum[wid] = s;
        __syncthreads();
        if (tid == 0) {
            float t = ssum[0] + ssum[1] + ssum[2] + ssum[3];
            out[0] = t / (262144.0f * (float)(BC * BINS));
            g_count = 0u;                      // restore ticket for replay
        }
    }
}

extern "C" void kernel_launch(void* const* d_in, const int* in_sizes, int n_in,
                              void* d_out, int out_size) {
    const float* inp = (const float*)d_in[0];
    const float* tgt = (const float*)d_in[1];
    float* out = (float*)d_out;

    dim3 grid(BC, BPP);                        // 96 x 21 = 2016 blocks
    fused_kernel<<<grid, THREADS>>>((const float4*)inp, (const float4*)tgt, out);
}

// round 14
// speedup vs baseline: 1.4355x; 1.4355x over previous
#include <cuda_runtime.h>

#define BINS 64
#define BC 96                      // B*C = 32*3
#define PLANE4 65536               // 512*512/4 float4 per (b,c) plane
#define BPP 24                     // chunks per plane
#define THREADS 128
#define WARPS (THREADS / 32)       // 4
#define GRID (BC * BPP)            // 2304 <= 148*16 = 2368 -> SINGLE WAVE

// Signed per-(plane,bin) count diff (+input, -target). Zero at module load;
// the last block restores it to zero each call -> graph-replay safe.
__device__ int g_diff[BC * BINS];
__device__ unsigned int g_count;

// bin = clip(floor((v+1)/step), 0, 63). Input domain [-1,1) => result >= 0.
// Exact-edge disagreement with searchsorted is ~1e-6 relative loss noise.
__device__ __forceinline__ int bin_of(float v) {
    return min(__float2int_rd(fmaf(v, 31.5f, 31.5f)), 63);
}

// s8 packing, 4 bins/word: byte = lane*4 + (bin>>2)*128 + (bin&3)
// -> word = (bin>>2)*32 + lane, so word % 32 == lane for EVERY bin:
// strictly conflict-free LDS/STS, and each lane owns its words (no races).
__device__ __forceinline__ int off_of(int b) {
    return ((b & ~3) << 5) | (b & 3);          // (bin>>2)*128 + (bin&3)
}

__global__ __launch_bounds__(THREADS, 16)      // thread-limited: 16 blk/SM
void fused_kernel(const float4* __restrict__ inp, const float4* __restrict__ tgt,
                  float* __restrict__ out) {
    __shared__ signed char hist[WARPS * 2048]; // 8 KB -> occupancy is
    __shared__ unsigned int s_ticket;          // thread-limited, not smem
    __shared__ float ssum[WARPS];

    const int tid  = threadIdx.x;
    const int lane = tid & 31;
    const int wid  = tid >> 5;

    int4* z4 = (int4*)hist;
    #pragma unroll
    for (int i = tid; i < (int)sizeof(hist) / 16; i += THREADS)
        z4[i] = make_int4(0, 0, 0, 0);
    __syncthreads();

    signed char* h = &hist[wid * 2048 + lane * 4];   // lane-owned byte column

    const int plane = blockIdx.x / BPP;
    const int chunk = blockIdx.x % BPP;
    // Exact uneven bounds (PLANE4 not divisible by 24).
    const int start4 = (chunk * PLANE4) / BPP;
    const int end4   = ((chunk + 1) * PLANE4) / BPP;
    const float4* __restrict__ a = inp + (size_t)plane * PLANE4;
    const float4* __restrict__ b = tgt + (size_t)plane * PLANE4;

    // Max ~22 iters x 4 values per tensor -> per-bin diff in [-88, 88]: s8 ok.
    for (int i = start4 + tid; i < end4; i += THREADS) {
        float4 v = __ldcs(&a[i]);              // read-once: streaming
        float4 u = __ldcs(&b[i]);
        h[off_of(bin_of(v.x))] += 1;
        h[off_of(bin_of(v.y))] += 1;
        h[off_of(bin_of(v.z))] += 1;
        h[off_of(bin_of(v.w))] += 1;
        h[off_of(bin_of(u.x))] -= 1;
        h[off_of(bin_of(u.y))] -= 1;
        h[off_of(bin_of(u.z))] -= 1;
        h[off_of(bin_of(u.w))] -= 1;
    }
    __syncthreads();

    // Fold: thread t -> bin = t&63, half = t>>6 (warps 2h, 2h+1). Extract
    // byte (bin&3) from 2 warps x 32 lane-words via masked signed dp4a.
    // Lane rotation (l+t)&31 -> distinct banks within the folding warp.
    {
        const int bin  = tid & 63;
        const int half = tid >> 6;
        const int mask = 1 << ((bin & 3) * 8);
        int s = 0;
        #pragma unroll
        for (int w = 0; w < 2; w++) {
            const int* row = (const int*)hist + (2 * half + w) * 512 + (bin >> 2) * 32;
            #pragma unroll
            for (int l = 0; l < 32; l++)
                s = __dp4a(row[(l + tid) & 31], mask, s);
        }
        if (s != 0) atomicAdd(&g_diff[plane * BINS + bin], s);
    }

    // Last block finishes the reduction (no separate kernel launch).
    __threadfence();
    if (tid == 0) s_ticket = atomicAdd(&g_count, 1u);
    __syncthreads();
    if (s_ticket == GRID - 1) {
        float s = 0.0f;
        for (int i = tid; i < BC * BINS; i += THREADS) {
            s += fabsf((float)__ldcg(&g_diff[i]));
            g_diff[i] = 0;                     // restore scratch for replay
        }
        #pragma unroll
        for (int o = 16; o > 0; o >>= 1)
            s += __shfl_down_sync(0xFFFFFFFFu, s, o);
        if (lane == 0) ssum[wid] = s;
        __syncthreads();
        if (tid == 0) {
            float t = ssum[0] + ssum[1] + ssum[2] + ssum[3];
            out[0] = t / (262144.0f * (float)(BC * BINS));
            g_count = 0u;                      // restore ticket for replay
        }
    }
}

extern "C" void kernel_launch(void* const* d_in, const int* in_sizes, int n_in,
                              void* d_out, int out_size) {
    const float* inp = (const float*)d_in[0];
    const float* tgt = (const float*)d_in[1];
    float* out = (float*)d_out;

    fused_kernel<<<GRID, THREADS>>>((const float4*)inp, (const float4*)tgt, out);
}